// round 1
// baseline (speedup 1.0000x reference)
#include <cuda_runtime.h>
#include <math.h>

#define BB 2
#define TT 2048
#define DIN 1024
#define EE 64
#define HH 16
#define EH 1024
#define MM (BB*TT)

// Scratch: q,k in [b,h,e,t] (contraction-major), v,o in [b,h,t,e]
__device__ float g_q[BB*HH*EE*TT];
__device__ float g_k[BB*HH*EE*TT];
__device__ float g_v[BB*HH*TT*EE];
__device__ float g_o[BB*HH*TT*EE];

__device__ __forceinline__ void ld4(float* d, const float* s) {
    float4 t = *(const float4*)s;
    d[0] = t.x; d[1] = t.y; d[2] = t.z; d[3] = t.w;
}

// ---------------------------------------------------------------------------
// Kernel 1: QKV projection. Y = X @ W for W in {Wq, Wk, Wv}; epilogue
// de-interleaves heads (n = e*16 + h) into head-planar scratch layouts.
// Tiles: 64x64, K-tile 16, 256 threads, 4x4 per thread.
// ---------------------------------------------------------------------------
__global__ __launch_bounds__(256) void qkv_kernel(
    const float* __restrict__ inp,
    const float* __restrict__ Wq,
    const float* __restrict__ Wk,
    const float* __restrict__ Wv)
{
    __shared__ __align__(16) float As[16*68];  // [k][m]
    __shared__ __align__(16) float Bs[16*68];  // [k][n]

    const float* W;
    float* dst;
    int emajor;
    if (blockIdx.z == 0)      { W = Wq; dst = g_q; emajor = 1; }
    else if (blockIdx.z == 1) { W = Wk; dst = g_k; emajor = 1; }
    else                      { W = Wv; dst = g_v; emajor = 0; }

    const int m0 = blockIdx.x * 64;
    const int n0 = blockIdx.y * 64;
    const int tid = threadIdx.x;
    const int ty = tid >> 4, tx = tid & 15;

    float acc[4][4] = {};

    const int am = tid >> 2, akg = tid & 3;    // A load: row, float4 group
    const int bk = tid >> 4, bng = tid & 15;   // B load: k row, float4 group

    for (int k0 = 0; k0 < DIN; k0 += 16) {
        float4 a4 = *(const float4*)(inp + (m0 + am) * DIN + k0 + akg * 4);
        As[(akg*4 + 0)*68 + am] = a4.x;
        As[(akg*4 + 1)*68 + am] = a4.y;
        As[(akg*4 + 2)*68 + am] = a4.z;
        As[(akg*4 + 3)*68 + am] = a4.w;
        *(float4*)(Bs + bk*68 + bng*4) =
            *(const float4*)(W + (k0 + bk) * EH + n0 + bng * 4);
        __syncthreads();

        #pragma unroll
        for (int k = 0; k < 16; k++) {
            float a[4], b[4];
            ld4(a, As + k*68 + ty*4);
            ld4(b, Bs + k*68 + tx*4);
            #pragma unroll
            for (int i = 0; i < 4; i++)
                #pragma unroll
                for (int j = 0; j < 4; j++)
                    acc[i][j] += a[i] * b[j];
        }
        __syncthreads();
    }

    #pragma unroll
    for (int i = 0; i < 4; i++) {
        #pragma unroll
        for (int j = 0; j < 4; j++) {
            int m = m0 + ty*4 + i;
            int n = n0 + tx*4 + j;
            int b = m >> 11, t = m & 2047;
            int e = n >> 4,  h = n & 15;
            int bh = b * HH + h;
            if (emajor) dst[bh * (EE*TT) + e * TT + t] = acc[i][j];
            else        dst[bh * (TT*EE) + t * EE + e] = acc[i][j];
        }
    }
}

// ---------------------------------------------------------------------------
// Kernel 2: flash-attention, causal. CTA = 64 query rows of one (b,h).
// Qs/Ks e-major [64e][64x], Vs [64c][64e], Ps [64r][64c]; stride 68.
// Online softmax with shuffle reductions over the 16-lane tx group.
// ---------------------------------------------------------------------------
__global__ __launch_bounds__(256) void attn_kernel()
{
    extern __shared__ __align__(16) float sm[];
    float* Qs = sm;               // [e][r]
    float* Ks = sm + 64*68;       // [e][c]
    float* Vs = sm + 2*64*68;     // [c][e]
    float* Ps = sm + 3*64*68;     // [r][c]

    const int qt = (int)(gridDim.x - 1) - (int)blockIdx.x;  // big tiles first
    const int bh = blockIdx.y;
    const int r0 = qt * 64;
    const int tid = threadIdx.x;
    const int ty = tid >> 4, tx = tid & 15;

    const float* qpl = g_q + bh * (EE*TT);
    const float* kpl = g_k + bh * (EE*TT);
    const float* vpl = g_v + bh * (TT*EE);

    // Load Q tile (pre-scaled by 1/sqrt(E) = 0.125)
    for (int s = tid; s < 64*16; s += 256) {
        int er = s >> 4, cg = s & 15;
        float4 v4 = *(const float4*)(qpl + er * TT + r0 + cg * 4);
        v4.x *= 0.125f; v4.y *= 0.125f; v4.z *= 0.125f; v4.w *= 0.125f;
        *(float4*)(Qs + er*68 + cg*4) = v4;
    }

    float o[4][4] = {};
    float mi[4] = {-INFINITY, -INFINITY, -INFINITY, -INFINITY};
    float li[4] = {0.f, 0.f, 0.f, 0.f};

    for (int kt = 0; kt <= qt; kt++) {
        const int c0 = kt * 64;
        __syncthreads();  // previous tile's consumers done before overwrite
        for (int s = tid; s < 64*16; s += 256) {
            int r = s >> 4, g = s & 15;
            *(float4*)(Ks + r*68 + g*4) =
                *(const float4*)(kpl + r * TT + c0 + g * 4);
            *(float4*)(Vs + r*68 + g*4) =
                *(const float4*)(vpl + (c0 + r) * EE + g * 4);
        }
        __syncthreads();

        // S = (Q/8) K^T
        float s_[4][4] = {};
        #pragma unroll 8
        for (int e = 0; e < 64; e++) {
            float q[4], k[4];
            ld4(q, Qs + e*68 + ty*4);
            ld4(k, Ks + e*68 + tx*4);
            #pragma unroll
            for (int i = 0; i < 4; i++)
                #pragma unroll
                for (int j = 0; j < 4; j++)
                    s_[i][j] += q[i] * k[j];
        }

        if (kt == qt) {  // causal mask on diagonal tile
            #pragma unroll
            for (int i = 0; i < 4; i++)
                #pragma unroll
                for (int j = 0; j < 4; j++)
                    if (tx*4 + j > ty*4 + i) s_[i][j] = -1e30f;
        }

        // online softmax
        #pragma unroll
        for (int i = 0; i < 4; i++) {
            float tm = fmaxf(fmaxf(s_[i][0], s_[i][1]), fmaxf(s_[i][2], s_[i][3]));
            #pragma unroll
            for (int off = 8; off > 0; off >>= 1)
                tm = fmaxf(tm, __shfl_xor_sync(0xffffffffu, tm, off));
            float nm = fmaxf(mi[i], tm);
            float corr = __expf(mi[i] - nm);
            float rs = 0.f;
            #pragma unroll
            for (int j = 0; j < 4; j++) {
                s_[i][j] = __expf(s_[i][j] - nm);
                rs += s_[i][j];
            }
            #pragma unroll
            for (int off = 8; off > 0; off >>= 1)
                rs += __shfl_xor_sync(0xffffffffu, rs, off);
            li[i] = li[i] * corr + rs;
            mi[i] = nm;
            #pragma unroll
            for (int j = 0; j < 4; j++) o[i][j] *= corr;
            float4 p4 = make_float4(s_[i][0], s_[i][1], s_[i][2], s_[i][3]);
            *(float4*)(Ps + (ty*4 + i)*68 + tx*4) = p4;
        }
        __syncthreads();

        // O += P V
        #pragma unroll 4
        for (int cb = 0; cb < 64; cb += 4) {
            float pr[4][4];
            ld4(pr[0], Ps + (ty*4 + 0)*68 + cb);
            ld4(pr[1], Ps + (ty*4 + 1)*68 + cb);
            ld4(pr[2], Ps + (ty*4 + 2)*68 + cb);
            ld4(pr[3], Ps + (ty*4 + 3)*68 + cb);
            #pragma unroll
            for (int cc = 0; cc < 4; cc++) {
                float v[4];
                ld4(v, Vs + (cb + cc)*68 + tx*4);
                #pragma unroll
                for (int i = 0; i < 4; i++)
                    #pragma unroll
                    for (int j = 0; j < 4; j++)
                        o[i][j] += pr[i][cc] * v[j];
            }
        }
    }

    // epilogue: normalize, write to g_o [b,h,t,e]
    #pragma unroll
    for (int i = 0; i < 4; i++) {
        float inv = 1.0f / li[i];
        float4 r;
        r.x = o[i][0] * inv; r.y = o[i][1] * inv;
        r.z = o[i][2] * inv; r.w = o[i][3] * inv;
        *(float4*)(g_o + bh * (TT*EE) + (r0 + ty*4 + i) * EE + tx*4) = r;
    }
}

// ---------------------------------------------------------------------------
// Kernel 3: output projection. out[m, :64] = A[m, :1024] @ Wu + bu,
// A[m, e*16+h] = g_o[b,h,t,e]. K-tile of 16 == one e with all 16 h.
// ---------------------------------------------------------------------------
__global__ __launch_bounds__(256) void proj_kernel(
    const float* __restrict__ Wu,
    const float* __restrict__ bu,
    float* __restrict__ out)
{
    __shared__ __align__(16) float As[16*68];  // [k][m]
    __shared__ __align__(16) float Bs[16*68];  // [k][n]

    const int m0 = blockIdx.x * 64;
    const int tid = threadIdx.x;
    const int ty = tid >> 4, tx = tid & 15;

    float acc[4][4] = {};

    for (int k0 = 0; k0 < EH; k0 += 16) {
        const int e0 = k0 >> 4;   // this k-tile = all 16 heads at e = e0
        for (int s = tid; s < 1024; s += 256) {
            int k = s >> 6, mm = s & 63;   // k == h
            int gm = m0 + mm;
            int b = gm >> 11, t = gm & 2047;
            As[k*68 + mm] = g_o[(b * HH + k) * (TT*EE) + t * EE + e0];
        }
        {
            int k = tid >> 4, ng = tid & 15;
            *(float4*)(Bs + k*68 + ng*4) =
                *(const float4*)(Wu + (k0 + k) * EE + ng * 4);
        }
        __syncthreads();

        #pragma unroll
        for (int k = 0; k < 16; k++) {
            float a[4], b[4];
            ld4(a, As + k*68 + ty*4);
            ld4(b, Bs + k*68 + tx*4);
            #pragma unroll
            for (int i = 0; i < 4; i++)
                #pragma unroll
                for (int j = 0; j < 4; j++)
                    acc[i][j] += a[i] * b[j];
        }
        __syncthreads();
    }

    float4 bias = *(const float4*)(bu + tx * 4);
    #pragma unroll
    for (int i = 0; i < 4; i++) {
        int gm = m0 + ty*4 + i;
        float4 r;
        r.x = acc[i][0] + bias.x;
        r.y = acc[i][1] + bias.y;
        r.z = acc[i][2] + bias.z;
        r.w = acc[i][3] + bias.w;
        *(float4*)(out + gm * EE + tx * 4) = r;
    }
}

// ---------------------------------------------------------------------------
extern "C" void kernel_launch(void* const* d_in, const int* in_sizes, int n_in,
                              void* d_out, int out_size)
{
    const float* inp = (const float*)d_in[0];
    // d_in[1] is the causal mask; causality is implemented directly.
    const float* Wq = (const float*)d_in[2];
    const float* Wk = (const float*)d_in[3];
    const float* Wv = (const float*)d_in[4];
    const float* Wu = (const float*)d_in[5];
    const float* bu = (const float*)d_in[6];
    float* out = (float*)d_out;

    cudaFuncSetAttribute(attn_kernel,
                         cudaFuncAttributeMaxDynamicSharedMemorySize,
                         4 * 64 * 68 * (int)sizeof(float));

    dim3 g1(MM/64, EH/64, 3);
    qkv_kernel<<<g1, 256>>>(inp, Wq, Wk, Wv);

    dim3 g2(TT/64, BB*HH);
    attn_kernel<<<g2, 256, 4 * 64 * 68 * sizeof(float)>>>();

    proj_kernel<<<MM/64, 256>>>(Wu, bu, out);
}

// round 2
// speedup vs baseline: 1.0698x; 1.0698x over previous
#include <cuda_runtime.h>
#include <math.h>

#define BB 2
#define TT 2048
#define DIN 1024
#define EE 64
#define HH 16
#define EH 1024
#define MM (BB*TT)

// Scratch: q,k in [b,h,e,t] (contraction-major), v,o in [b,h,t,e]
__device__ float g_q[BB*HH*EE*TT];
__device__ float g_k[BB*HH*EE*TT];
__device__ float g_v[BB*HH*TT*EE];
__device__ float g_o[BB*HH*TT*EE];

__device__ __forceinline__ void ld4(float* d, const float* s) {
    float4 t = *(const float4*)s;
    d[0] = t.x; d[1] = t.y; d[2] = t.z; d[3] = t.w;
}

// ---------------------------------------------------------------------------
// Kernel 1: QKV projection. 128x128 CTA tile, 8x8 microtile (cols/rows split
// as {q*4, 64+q*4} for conflict-free LDS.128), K-tile 16, 256 threads.
// Epilogue de-interleaves heads (n = e*16 + h) into head-planar layouts.
// ---------------------------------------------------------------------------
__global__ __launch_bounds__(256, 2) void qkv_kernel(
    const float* __restrict__ inp,
    const float* __restrict__ Wq,
    const float* __restrict__ Wk,
    const float* __restrict__ Wv)
{
    __shared__ __align__(16) float As[16*132];  // [k][m]
    __shared__ __align__(16) float Bs[16*132];  // [k][n]

    const float* W;
    float* dst;
    int emajor;
    if (blockIdx.z == 0)      { W = Wq; dst = g_q; emajor = 1; }
    else if (blockIdx.z == 1) { W = Wk; dst = g_k; emajor = 1; }
    else                      { W = Wv; dst = g_v; emajor = 0; }

    const int m0 = blockIdx.x * 128;
    const int n0 = blockIdx.y * 128;
    const int tid = threadIdx.x;
    const int ty = tid >> 4, tx = tid & 15;

    float acc[8][8] = {};

    const int arow = tid >> 1;           // 0..127
    const int agrp = (tid & 1) * 2;      // base float4 group (of 4 per row)
    const int bk = tid >> 4;             // 0..15
    const int bng = tid & 15;            // 0..15 (two passes for 32 groups)

    for (int k0 = 0; k0 < DIN; k0 += 16) {
        #pragma unroll
        for (int l = 0; l < 2; l++) {
            float4 a4 = *(const float4*)(inp + (m0 + arow) * DIN + k0 + (agrp + l) * 4);
            As[((agrp + l)*4 + 0)*132 + arow] = a4.x;
            As[((agrp + l)*4 + 1)*132 + arow] = a4.y;
            As[((agrp + l)*4 + 2)*132 + arow] = a4.z;
            As[((agrp + l)*4 + 3)*132 + arow] = a4.w;
        }
        #pragma unroll
        for (int l = 0; l < 2; l++) {
            int ng = bng + l*16;
            *(float4*)(Bs + bk*132 + ng*4) =
                *(const float4*)(W + (k0 + bk) * EH + n0 + ng * 4);
        }
        __syncthreads();

        #pragma unroll
        for (int k = 0; k < 16; k++) {
            float a[8], b[8];
            ld4(a,     As + k*132 + ty*4);
            ld4(a + 4, As + k*132 + 64 + ty*4);
            ld4(b,     Bs + k*132 + tx*4);
            ld4(b + 4, Bs + k*132 + 64 + tx*4);
            #pragma unroll
            for (int i = 0; i < 8; i++)
                #pragma unroll
                for (int j = 0; j < 8; j++)
                    acc[i][j] += a[i] * b[j];
        }
        __syncthreads();
    }

    #pragma unroll
    for (int i = 0; i < 8; i++) {
        int m = m0 + (i >> 2)*64 + ty*4 + (i & 3);
        int b = m >> 11, t = m & 2047;
        #pragma unroll
        for (int j = 0; j < 8; j++) {
            int n = n0 + (j >> 2)*64 + tx*4 + (j & 3);
            int e = n >> 4,  h = n & 15;
            int bh = b * HH + h;
            if (emajor) dst[bh * (EE*TT) + e * TT + t] = acc[i][j];
            else        dst[bh * (TT*EE) + t * EE + e] = acc[i][j];
        }
    }
}

// ---------------------------------------------------------------------------
// Kernel 2: flash-attention, causal. CTA = 128 query rows of one (b,h),
// inner tiles of 64 keys. 8x4 microtile (rows split {ty*4, 64+ty*4}).
// Qs [e][r] stride 132, Ks/Vs stride 68, Ps [r][c] stride 68. ~101KB smem.
// ---------------------------------------------------------------------------
__global__ __launch_bounds__(256, 2) void attn_kernel()
{
    extern __shared__ __align__(16) float sm[];
    float* Qs = sm;                    // [64 e][132] (128 r used)
    float* Ks = sm + 64*132;           // [64 e][68]  (64 c used)
    float* Vs = sm + 64*132 + 64*68;   // [64 c][68]  (64 e used)
    float* Ps = sm + 64*132 + 2*64*68; // [128 r][68] (64 c used)

    const int qt = (int)(gridDim.x - 1) - (int)blockIdx.x;  // big tiles first
    const int bh = blockIdx.y;
    const int r0 = qt * 128;
    const int tid = threadIdx.x;
    const int ty = tid >> 4, tx = tid & 15;

    const float* qpl = g_q + bh * (EE*TT);
    const float* kpl = g_k + bh * (EE*TT);
    const float* vpl = g_v + bh * (TT*EE);

    // Load Q tile (pre-scaled by 1/sqrt(E) = 0.125): 64 e x 128 r
    for (int s = tid; s < 64*32; s += 256) {
        int er = s >> 5, cg = s & 31;
        float4 v4 = *(const float4*)(qpl + er * TT + r0 + cg * 4);
        v4.x *= 0.125f; v4.y *= 0.125f; v4.z *= 0.125f; v4.w *= 0.125f;
        *(float4*)(Qs + er*132 + cg*4) = v4;
    }

    float o[8][4] = {};
    float mi[8], li[8];
    #pragma unroll
    for (int i = 0; i < 8; i++) { mi[i] = -INFINITY; li[i] = 0.f; }

    const int nkt = 2*qt + 2;
    for (int kt = 0; kt < nkt; kt++) {
        const int c0 = kt * 64;
        __syncthreads();  // previous tile's consumers done before overwrite
        for (int s = tid; s < 64*16; s += 256) {
            int r = s >> 4, g = s & 15;
            *(float4*)(Ks + r*68 + g*4) =
                *(const float4*)(kpl + r * TT + c0 + g * 4);
            *(float4*)(Vs + r*68 + g*4) =
                *(const float4*)(vpl + (c0 + r) * EE + g * 4);
        }
        __syncthreads();

        // S = (Q/8) K^T : 128 x 64
        float s_[8][4] = {};
        #pragma unroll 8
        for (int e = 0; e < 64; e++) {
            float q[8], k[4];
            ld4(q,     Qs + e*132 + ty*4);
            ld4(q + 4, Qs + e*132 + 64 + ty*4);
            ld4(k,     Ks + e*68 + tx*4);
            #pragma unroll
            for (int i = 0; i < 8; i++)
                #pragma unroll
                for (int j = 0; j < 4; j++)
                    s_[i][j] += q[i] * k[j];
        }

        if (kt >= 2*qt) {  // only last two tiles touch the diagonal
            #pragma unroll
            for (int i = 0; i < 8; i++) {
                int rg = r0 + (i >> 2)*64 + ty*4 + (i & 3);
                #pragma unroll
                for (int j = 0; j < 4; j++)
                    if (c0 + tx*4 + j > rg) s_[i][j] = -1e30f;
            }
        }

        // online softmax (row groups of 16 lanes x 4 cols)
        #pragma unroll
        for (int i = 0; i < 8; i++) {
            float tm = fmaxf(fmaxf(s_[i][0], s_[i][1]), fmaxf(s_[i][2], s_[i][3]));
            #pragma unroll
            for (int off = 8; off > 0; off >>= 1)
                tm = fmaxf(tm, __shfl_xor_sync(0xffffffffu, tm, off));
            float nm = fmaxf(mi[i], tm);
            float corr = __expf(mi[i] - nm);
            float rs = 0.f;
            #pragma unroll
            for (int j = 0; j < 4; j++) {
                s_[i][j] = __expf(s_[i][j] - nm);
                rs += s_[i][j];
            }
            #pragma unroll
            for (int off = 8; off > 0; off >>= 1)
                rs += __shfl_xor_sync(0xffffffffu, rs, off);
            li[i] = li[i] * corr + rs;
            mi[i] = nm;
            #pragma unroll
            for (int j = 0; j < 4; j++) o[i][j] *= corr;
            int rr = (i >> 2)*64 + ty*4 + (i & 3);
            *(float4*)(Ps + rr*68 + tx*4) =
                make_float4(s_[i][0], s_[i][1], s_[i][2], s_[i][3]);
        }
        __syncthreads();

        // O += P V  (128 x 64 @ 64 x 64)
        #pragma unroll 4
        for (int cb = 0; cb < 64; cb += 4) {
            float pr[8][4];
            #pragma unroll
            for (int i = 0; i < 8; i++) {
                int rr = (i >> 2)*64 + ty*4 + (i & 3);
                ld4(pr[i], Ps + rr*68 + cb);
            }
            #pragma unroll
            for (int cc = 0; cc < 4; cc++) {
                float v[4];
                ld4(v, Vs + (cb + cc)*68 + tx*4);
                #pragma unroll
                for (int i = 0; i < 8; i++)
                    #pragma unroll
                    for (int j = 0; j < 4; j++)
                        o[i][j] += pr[i][cc] * v[j];
            }
        }
    }

    // epilogue: normalize, write to g_o [b,h,t,e]
    #pragma unroll
    for (int i = 0; i < 8; i++) {
        float inv = 1.0f / li[i];
        int rr = (i >> 2)*64 + ty*4 + (i & 3);
        float4 r;
        r.x = o[i][0] * inv; r.y = o[i][1] * inv;
        r.z = o[i][2] * inv; r.w = o[i][3] * inv;
        *(float4*)(g_o + bh * (TT*EE) + (r0 + rr) * EE + tx*4) = r;
    }
}

// ---------------------------------------------------------------------------
// Kernel 3: output projection. out[m, :64] = A[m, :1024] @ Wu + bu,
// A[m, e*16+h] = g_o[b,h,t,e]. K-tile of 16 == one e with all 16 h.
// ---------------------------------------------------------------------------
__global__ __launch_bounds__(256) void proj_kernel(
    const float* __restrict__ Wu,
    const float* __restrict__ bu,
    float* __restrict__ out)
{
    __shared__ __align__(16) float As[16*68];  // [k][m]
    __shared__ __align__(16) float Bs[16*68];  // [k][n]

    const int m0 = blockIdx.x * 64;
    const int tid = threadIdx.x;
    const int ty = tid >> 4, tx = tid & 15;

    float acc[4][4] = {};

    for (int k0 = 0; k0 < EH; k0 += 16) {
        const int e0 = k0 >> 4;   // this k-tile = all 16 heads at e = e0
        for (int s = tid; s < 1024; s += 256) {
            int k = s >> 6, mm = s & 63;   // k == h
            int gm = m0 + mm;
            int b = gm >> 11, t = gm & 2047;
            As[k*68 + mm] = g_o[(b * HH + k) * (TT*EE) + t * EE + e0];
        }
        {
            int k = tid >> 4, ng = tid & 15;
            *(float4*)(Bs + k*68 + ng*4) =
                *(const float4*)(Wu + (k0 + k) * EE + ng * 4);
        }
        __syncthreads();

        #pragma unroll
        for (int k = 0; k < 16; k++) {
            float a[4], b[4];
            ld4(a, As + k*68 + ty*4);
            ld4(b, Bs + k*68 + tx*4);
            #pragma unroll
            for (int i = 0; i < 4; i++)
                #pragma unroll
                for (int j = 0; j < 4; j++)
                    acc[i][j] += a[i] * b[j];
        }
        __syncthreads();
    }

    float4 bias = *(const float4*)(bu + tx * 4);
    #pragma unroll
    for (int i = 0; i < 4; i++) {
        int gm = m0 + ty*4 + i;
        float4 r;
        r.x = acc[i][0] + bias.x;
        r.y = acc[i][1] + bias.y;
        r.z = acc[i][2] + bias.z;
        r.w = acc[i][3] + bias.w;
        *(float4*)(out + gm * EE + tx * 4) = r;
    }
}

// ---------------------------------------------------------------------------
extern "C" void kernel_launch(void* const* d_in, const int* in_sizes, int n_in,
                              void* d_out, int out_size)
{
    const float* inp = (const float*)d_in[0];
    // d_in[1] is the causal mask; causality is implemented directly.
    const float* Wq = (const float*)d_in[2];
    const float* Wk = (const float*)d_in[3];
    const float* Wv = (const float*)d_in[4];
    const float* Wu = (const float*)d_in[5];
    const float* bu = (const float*)d_in[6];
    float* out = (float*)d_out;

    const int attn_smem = (64*132 + 2*64*68 + 128*68) * (int)sizeof(float);
    cudaFuncSetAttribute(attn_kernel,
                         cudaFuncAttributeMaxDynamicSharedMemorySize, attn_smem);

    dim3 g1(MM/128, EH/128, 3);
    qkv_kernel<<<g1, 256>>>(inp, Wq, Wk, Wv);

    dim3 g2(TT/128, BB*HH);
    attn_kernel<<<g2, 256, attn_smem>>>();

    proj_kernel<<<MM/64, 256>>>(Wu, bu, out);
}

// round 3
// speedup vs baseline: 1.1180x; 1.0451x over previous
#include <cuda_runtime.h>
#include <math.h>
#include <stdint.h>

#define BB 2
#define TT 2048
#define DIN 1024
#define EE 64
#define HH 16
#define EH 1024
#define MM (BB*TT)

// Scratch: xt = X^T [k][m]; q,k in [b,h,e,t]; v,o in [b,h,t,e]
__device__ float g_xt[DIN*MM];
__device__ float g_q[BB*HH*EE*TT];
__device__ float g_k[BB*HH*EE*TT];
__device__ float g_v[BB*HH*TT*EE];
__device__ float g_o[BB*HH*TT*EE];

__device__ __forceinline__ void ld4(float* d, const float* s) {
    float4 t = *(const float4*)s;
    d[0] = t.x; d[1] = t.y; d[2] = t.z; d[3] = t.w;
}

__device__ __forceinline__ void cpa16(uint32_t dst, const float* src) {
    asm volatile("cp.async.cg.shared.global [%0], [%1], 16;\n" :: "r"(dst), "l"(src));
}
__device__ __forceinline__ void cp_commit() {
    asm volatile("cp.async.commit_group;\n");
}
template<int N> __device__ __forceinline__ void cp_wait() {
    asm volatile("cp.async.wait_group %0;\n" :: "n"(N));
}

// ---------------------------------------------------------------------------
// Kernel 0: X [MM][DIN] -> g_xt [DIN][MM]
// ---------------------------------------------------------------------------
__global__ __launch_bounds__(256) void transpose_kernel(const float* __restrict__ in)
{
    __shared__ float t[32][33];
    const int m0 = blockIdx.x * 32, k0 = blockIdx.y * 32;
    const int x = threadIdx.x & 31, y = threadIdx.x >> 5;  // 32 x 8
    #pragma unroll
    for (int i = 0; i < 32; i += 8)
        t[y + i][x] = in[(m0 + y + i) * DIN + k0 + x];
    __syncthreads();
    #pragma unroll
    for (int i = 0; i < 32; i += 8)
        g_xt[(k0 + y + i) * MM + m0 + x] = t[x][y + i];
}

// ---------------------------------------------------------------------------
// Kernel 1: QKV projection, cp.async double-buffered.
// 128x128 CTA tile, 8x8 microtile, K-tile 16. A from g_xt [k][m], B from W
// [k][n] — both contiguous row copies. Epilogue de-interleaves heads.
// ---------------------------------------------------------------------------
__global__ __launch_bounds__(256, 2) void qkv_kernel(
    const float* __restrict__ Wq,
    const float* __restrict__ Wk,
    const float* __restrict__ Wv)
{
    __shared__ __align__(16) float As[2][16*128];  // [k][m]
    __shared__ __align__(16) float Bs[2][16*128];  // [k][n]

    const float* W;
    float* dst;
    int emajor;
    if (blockIdx.z == 0)      { W = Wq; dst = g_q; emajor = 1; }
    else if (blockIdx.z == 1) { W = Wk; dst = g_k; emajor = 1; }
    else                      { W = Wv; dst = g_v; emajor = 0; }

    const int m0 = blockIdx.x * 128;
    const int n0 = blockIdx.y * 128;
    const int tid = threadIdx.x;
    const int ty = tid >> 4, tx = tid & 15;

    const uint32_t sA = (uint32_t)__cvta_generic_to_shared(&As[0][0]);
    const uint32_t sB = (uint32_t)__cvta_generic_to_shared(&Bs[0][0]);

    // fill mapping: s in [0,512): row = s>>5 (16 rows), chunk = s&31
    const int fr0 = tid >> 5,        fc0 = tid & 31;        // s = tid
    const int fr1 = (tid + 256) >> 5, fc1 = tid & 31;        // s = tid + 256

    auto issue = [&](int k0, int buf) {
        const float* a0 = g_xt + (k0 + fr0) * MM + m0 + fc0 * 4;
        const float* a1 = g_xt + (k0 + fr1) * MM + m0 + fc1 * 4;
        const float* b0 = W + (k0 + fr0) * EH + n0 + fc0 * 4;
        const float* b1 = W + (k0 + fr1) * EH + n0 + fc1 * 4;
        uint32_t oa = buf * (16*128*4);
        cpa16(sA + oa + (fr0*128 + fc0*4)*4, a0);
        cpa16(sA + oa + (fr1*128 + fc1*4)*4, a1);
        cpa16(sB + oa + (fr0*128 + fc0*4)*4, b0);
        cpa16(sB + oa + (fr1*128 + fc1*4)*4, b1);
        cp_commit();
    };

    float acc[8][8] = {};

    issue(0, 0);
    for (int t = 0; t < 64; t++) {
        cp_wait<0>();
        __syncthreads();
        const int buf = t & 1;
        issue(t < 63 ? (t + 1) * 16 : 0, buf ^ 1);

        const float* Ab = As[buf];
        const float* Bb = Bs[buf];
        #pragma unroll
        for (int k = 0; k < 16; k++) {
            float a[8], b[8];
            ld4(a,     Ab + k*128 + ty*4);
            ld4(a + 4, Ab + k*128 + 64 + ty*4);
            ld4(b,     Bb + k*128 + tx*4);
            ld4(b + 4, Bb + k*128 + 64 + tx*4);
            #pragma unroll
            for (int i = 0; i < 8; i++)
                #pragma unroll
                for (int j = 0; j < 8; j++)
                    acc[i][j] += a[i] * b[j];
        }
        __syncthreads();
    }

    #pragma unroll
    for (int i = 0; i < 8; i++) {
        int m = m0 + (i >> 2)*64 + ty*4 + (i & 3);
        int b = m >> 11, t = m & 2047;
        #pragma unroll
        for (int j = 0; j < 8; j++) {
            int n = n0 + (j >> 2)*64 + tx*4 + (j & 3);
            int e = n >> 4,  h = n & 15;
            int bh = b * HH + h;
            if (emajor) dst[bh * (EE*TT) + e * TT + t] = acc[i][j];
            else        dst[bh * (TT*EE) + t * EE + e] = acc[i][j];
        }
    }
}

// ---------------------------------------------------------------------------
// Kernel 2: flash-attention, causal, cp.async split-wait pipeline.
// CTA = 128 query rows of one (b,h), 64-wide K/V tiles, 8x4 microtile.
// K(kt+1) prefetch overlaps softmax+PV; V(kt+1) prefetch overlaps next S.
// ---------------------------------------------------------------------------
__global__ __launch_bounds__(256, 2) void attn_kernel()
{
    extern __shared__ __align__(16) float sm[];
    float* Qs = sm;                    // [64 e][132] (128 r used)
    float* Ks = sm + 64*132;           // [64 e][68]  (64 c used)
    float* Vs = sm + 64*132 + 64*68;   // [64 c][68]  (64 e used)
    float* Ps = sm + 64*132 + 2*64*68; // [128 r][68] (64 c used)

    const int qt = (int)(gridDim.x - 1) - (int)blockIdx.x;  // big tiles first
    const int bh = blockIdx.y;
    const int r0 = qt * 128;
    const int tid = threadIdx.x;
    const int ty = tid >> 4, tx = tid & 15;

    const float* qpl = g_q + bh * (EE*TT);
    const float* kpl = g_k + bh * (EE*TT);
    const float* vpl = g_v + bh * (TT*EE);

    const uint32_t sK = (uint32_t)__cvta_generic_to_shared(Ks);
    const uint32_t sV = (uint32_t)__cvta_generic_to_shared(Vs);

    // tile fill: s in [0,1024): r = s>>4, g = s&15; 4 chunks per thread
    auto issueK = [&](int c0) {
        #pragma unroll
        for (int l = 0; l < 4; l++) {
            int s = tid + l*256, r = s >> 4, g = s & 15;
            cpa16(sK + (r*68 + g*4)*4, kpl + r * TT + c0 + g * 4);
        }
        cp_commit();
    };
    auto issueV = [&](int c0) {
        #pragma unroll
        for (int l = 0; l < 4; l++) {
            int s = tid + l*256, r = s >> 4, g = s & 15;
            cpa16(sV + (r*68 + g*4)*4, vpl + (c0 + r) * EE + g * 4);
        }
        cp_commit();
    };

    const int nkt = 2*qt + 2;
    issueK(0);
    issueV(0);

    // Load Q tile (pre-scaled by 1/sqrt(E) = 0.125): 64 e x 128 r
    for (int s = tid; s < 64*32; s += 256) {
        int er = s >> 5, cg = s & 31;
        float4 v4 = *(const float4*)(qpl + er * TT + r0 + cg * 4);
        v4.x *= 0.125f; v4.y *= 0.125f; v4.z *= 0.125f; v4.w *= 0.125f;
        *(float4*)(Qs + er*132 + cg*4) = v4;
    }

    float o[8][4] = {};
    float mi[8], li[8];
    #pragma unroll
    for (int i = 0; i < 8; i++) { mi[i] = -INFINITY; li[i] = 0.f; }

    for (int kt = 0; kt < nkt; kt++) {
        const int c0 = kt * 64;

        cp_wait<1>();        // K(kt) done (V(kt) may still be in flight)
        __syncthreads();

        // S = (Q/8) K^T : 128 x 64
        float s_[8][4] = {};
        #pragma unroll 8
        for (int e = 0; e < 64; e++) {
            float q[8], k[4];
            ld4(q,     Qs + e*132 + ty*4);
            ld4(q + 4, Qs + e*132 + 64 + ty*4);
            ld4(k,     Ks + e*68 + tx*4);
            #pragma unroll
            for (int i = 0; i < 8; i++)
                #pragma unroll
                for (int j = 0; j < 4; j++)
                    s_[i][j] += q[i] * k[j];
        }
        __syncthreads();                       // all warps done reading Ks
        issueK(kt + 1 < nkt ? c0 + 64 : 0);    // overlaps softmax + PV

        if (kt >= 2*qt) {  // only last two tiles touch the diagonal
            #pragma unroll
            for (int i = 0; i < 8; i++) {
                int rg = r0 + (i >> 2)*64 + ty*4 + (i & 3);
                #pragma unroll
                for (int j = 0; j < 4; j++)
                    if (c0 + tx*4 + j > rg) s_[i][j] = -1e30f;
            }
        }

        // online softmax (row groups of 16 lanes x 4 cols)
        #pragma unroll
        for (int i = 0; i < 8; i++) {
            float tm = fmaxf(fmaxf(s_[i][0], s_[i][1]), fmaxf(s_[i][2], s_[i][3]));
            #pragma unroll
            for (int off = 8; off > 0; off >>= 1)
                tm = fmaxf(tm, __shfl_xor_sync(0xffffffffu, tm, off));
            float nm = fmaxf(mi[i], tm);
            float corr = __expf(mi[i] - nm);
            float rs = 0.f;
            #pragma unroll
            for (int j = 0; j < 4; j++) {
                s_[i][j] = __expf(s_[i][j] - nm);
                rs += s_[i][j];
            }
            #pragma unroll
            for (int off = 8; off > 0; off >>= 1)
                rs += __shfl_xor_sync(0xffffffffu, rs, off);
            li[i] = li[i] * corr + rs;
            mi[i] = nm;
            #pragma unroll
            for (int j = 0; j < 4; j++) o[i][j] *= corr;
            int rr = (i >> 2)*64 + ty*4 + (i & 3);
            *(float4*)(Ps + rr*68 + tx*4) =
                make_float4(s_[i][0], s_[i][1], s_[i][2], s_[i][3]);
        }

        cp_wait<1>();        // V(kt) done (K(kt+1) may still be in flight)
        __syncthreads();     // also publishes Ps

        // O += P V  (128 x 64 @ 64 x 64)
        #pragma unroll 4
        for (int cb = 0; cb < 64; cb += 4) {
            float pr[8][4];
            #pragma unroll
            for (int i = 0; i < 8; i++) {
                int rr = (i >> 2)*64 + ty*4 + (i & 3);
                ld4(pr[i], Ps + rr*68 + cb);
            }
            #pragma unroll
            for (int cc = 0; cc < 4; cc++) {
                float v[4];
                ld4(v, Vs + (cb + cc)*68 + tx*4);
                #pragma unroll
                for (int i = 0; i < 8; i++)
                    #pragma unroll
                    for (int j = 0; j < 4; j++)
                        o[i][j] += pr[i][cc] * v[j];
            }
        }
        __syncthreads();                       // all warps done reading Vs
        issueV(kt + 1 < nkt ? c0 + 64 : 0);    // overlaps next S phase
    }

    // epilogue: normalize, write to g_o [b,h,t,e]
    #pragma unroll
    for (int i = 0; i < 8; i++) {
        float inv = 1.0f / li[i];
        int rr = (i >> 2)*64 + ty*4 + (i & 3);
        float4 r;
        r.x = o[i][0] * inv; r.y = o[i][1] * inv;
        r.z = o[i][2] * inv; r.w = o[i][3] * inv;
        *(float4*)(g_o + bh * (TT*EE) + (r0 + rr) * EE + tx*4) = r;
    }
}

// ---------------------------------------------------------------------------
// Kernel 3: output projection. out[m, :64] = A[m, :1024] @ Wu + bu,
// A[m, e*16+h] = g_o[b,h,t,e]. K-tile of 16 == one e with all 16 h.
// ---------------------------------------------------------------------------
__global__ __launch_bounds__(256) void proj_kernel(
    const float* __restrict__ Wu,
    const float* __restrict__ bu,
    float* __restrict__ out)
{
    __shared__ __align__(16) float As[16*68];  // [k][m]
    __shared__ __align__(16) float Bs[16*68];  // [k][n]

    const int m0 = blockIdx.x * 64;
    const int tid = threadIdx.x;
    const int ty = tid >> 4, tx = tid & 15;

    float acc[4][4] = {};

    for (int k0 = 0; k0 < EH; k0 += 16) {
        const int e0 = k0 >> 4;   // this k-tile = all 16 heads at e = e0
        for (int s = tid; s < 1024; s += 256) {
            int k = s >> 6, mm = s & 63;   // k == h
            int gm = m0 + mm;
            int b = gm >> 11, t = gm & 2047;
            As[k*68 + mm] = g_o[(b * HH + k) * (TT*EE) + t * EE + e0];
        }
        {
            int k = tid >> 4, ng = tid & 15;
            *(float4*)(Bs + k*68 + ng*4) =
                *(const float4*)(Wu + (k0 + k) * EE + ng * 4);
        }
        __syncthreads();

        #pragma unroll
        for (int k = 0; k < 16; k++) {
            float a[4], b[4];
            ld4(a, As + k*68 + ty*4);
            ld4(b, Bs + k*68 + tx*4);
            #pragma unroll
            for (int i = 0; i < 4; i++)
                #pragma unroll
                for (int j = 0; j < 4; j++)
                    acc[i][j] += a[i] * b[j];
        }
        __syncthreads();
    }

    float4 bias = *(const float4*)(bu + tx * 4);
    #pragma unroll
    for (int i = 0; i < 4; i++) {
        int gm = m0 + ty*4 + i;
        float4 r;
        r.x = acc[i][0] + bias.x;
        r.y = acc[i][1] + bias.y;
        r.z = acc[i][2] + bias.z;
        r.w = acc[i][3] + bias.w;
        *(float4*)(out + gm * EE + tx * 4) = r;
    }
}

// ---------------------------------------------------------------------------
extern "C" void kernel_launch(void* const* d_in, const int* in_sizes, int n_in,
                              void* d_out, int out_size)
{
    const float* inp = (const float*)d_in[0];
    // d_in[1] is the causal mask; causality is implemented directly.
    const float* Wq = (const float*)d_in[2];
    const float* Wk = (const float*)d_in[3];
    const float* Wv = (const float*)d_in[4];
    const float* Wu = (const float*)d_in[5];
    const float* bu = (const float*)d_in[6];
    float* out = (float*)d_out;

    const int attn_smem = (64*132 + 2*64*68 + 128*68) * (int)sizeof(float);
    cudaFuncSetAttribute(attn_kernel,
                         cudaFuncAttributeMaxDynamicSharedMemorySize, attn_smem);

    dim3 g0(MM/32, DIN/32);
    transpose_kernel<<<g0, 256>>>(inp);

    dim3 g1(MM/128, EH/128, 3);
    qkv_kernel<<<g1, 256>>>(Wq, Wk, Wv);

    dim3 g2(TT/128, BB*HH);
    attn_kernel<<<g2, 256, attn_smem>>>();

    proj_kernel<<<MM/64, 256>>>(Wu, bu, out);
}

// round 5
// speedup vs baseline: 1.3979x; 1.2504x over previous
#include <cuda_runtime.h>
#include <cuda_bf16.h>
#include <math.h>
#include <stdint.h>

#define BB 2
#define TT 2048
#define DIN 1024
#define EE 64
#define HH 16
#define EH 1024
#define MM (BB*TT)

// bf16 split operands
__device__ __align__(16) __nv_bfloat16 g_xhi[MM*DIN];
__device__ __align__(16) __nv_bfloat16 g_xlo[MM*DIN];
__device__ __align__(16) __nv_bfloat16 g_wthi[3*EH*DIN];   // [z][n][k]
__device__ __align__(16) __nv_bfloat16 g_wtlo[3*EH*DIN];
// q,k in [b,h,e,t]; v,o in [b,h,t,e]
__device__ __align__(16) float g_q[BB*HH*EE*TT];
__device__ __align__(16) float g_k[BB*HH*EE*TT];
__device__ __align__(16) float g_v[BB*HH*TT*EE];
__device__ __align__(16) float g_o[BB*HH*TT*EE];

__device__ __forceinline__ void ld4(float* d, const float* s) {
    float4 t = *(const float4*)s;
    d[0] = t.x; d[1] = t.y; d[2] = t.z; d[3] = t.w;
}
__device__ __forceinline__ void cpa16(uint32_t dst, const void* src) {
    asm volatile("cp.async.cg.shared.global [%0], [%1], 16;\n" :: "r"(dst), "l"(src));
}
__device__ __forceinline__ void cp_commit() {
    asm volatile("cp.async.commit_group;\n");
}
template<int N> __device__ __forceinline__ void cp_wait() {
    asm volatile("cp.async.wait_group %0;\n" :: "n"(N));
}
__device__ __forceinline__ uint32_t smem_u32(const void* p) {
    uint32_t a;
    asm("{ .reg .u64 t; cvta.to.shared.u64 t, %1; cvt.u32.u64 %0, t; }" : "=r"(a) : "l"(p));
    return a;
}
__device__ __forceinline__ void mma_bf16(float* c, const uint32_t* a, const uint32_t* b) {
    asm volatile(
        "mma.sync.aligned.m16n8k16.row.col.f32.bf16.bf16.f32 "
        "{%0,%1,%2,%3}, {%4,%5,%6,%7}, {%8,%9}, {%0,%1,%2,%3};"
        : "+f"(c[0]), "+f"(c[1]), "+f"(c[2]), "+f"(c[3])
        : "r"(a[0]), "r"(a[1]), "r"(a[2]), "r"(a[3]), "r"(b[0]), "r"(b[1]));
}

// ---------------------------------------------------------------------------
// Prep: X f32 -> bf16 hi/lo (same [m][k] layout)
// ---------------------------------------------------------------------------
__global__ __launch_bounds__(256) void conv_x(const float* __restrict__ x)
{
    int i = (blockIdx.x * 256 + threadIdx.x) * 4;
    float4 v = *(const float4*)(x + i);
    __nv_bfloat16 h0 = __float2bfloat16(v.x), h1 = __float2bfloat16(v.y);
    __nv_bfloat16 h2 = __float2bfloat16(v.z), h3 = __float2bfloat16(v.w);
    __nv_bfloat16 l0 = __float2bfloat16(v.x - __bfloat162float(h0));
    __nv_bfloat16 l1 = __float2bfloat16(v.y - __bfloat162float(h1));
    __nv_bfloat16 l2 = __float2bfloat16(v.z - __bfloat162float(h2));
    __nv_bfloat16 l3 = __float2bfloat16(v.w - __bfloat162float(h3));
    *(__nv_bfloat162*)(g_xhi + i)     = __nv_bfloat162(h0, h1);
    *(__nv_bfloat162*)(g_xhi + i + 2) = __nv_bfloat162(h2, h3);
    *(__nv_bfloat162*)(g_xlo + i)     = __nv_bfloat162(l0, l1);
    *(__nv_bfloat162*)(g_xlo + i + 2) = __nv_bfloat162(l2, l3);
}

// ---------------------------------------------------------------------------
// Prep: W [k][n] f32 -> Wt [n][k] bf16 hi/lo, for each of Wq,Wk,Wv
// ---------------------------------------------------------------------------
__global__ __launch_bounds__(256) void conv_w(
    const float* __restrict__ Wq, const float* __restrict__ Wk,
    const float* __restrict__ Wv)
{
    const int z = blockIdx.z;
    const float* W = (z == 0) ? Wq : (z == 1) ? Wk : Wv;
    __shared__ float t[32][33];
    const int k0 = blockIdx.x * 32, n0 = blockIdx.y * 32;
    const int x = threadIdx.x & 31, y = threadIdx.x >> 5;
    #pragma unroll
    for (int i = 0; i < 32; i += 8)
        t[y + i][x] = W[(k0 + y + i) * EH + n0 + x];
    __syncthreads();
    #pragma unroll
    for (int i = 0; i < 32; i += 8) {
        float v = t[x][y + i];
        __nv_bfloat16 hi = __float2bfloat16(v);
        __nv_bfloat16 lo = __float2bfloat16(v - __bfloat162float(hi));
        size_t idx = (size_t)z * EH * DIN + (size_t)(n0 + y + i) * DIN + k0 + x;
        g_wthi[idx] = hi;
        g_wtlo[idx] = lo;
    }
}

// ---------------------------------------------------------------------------
// Kernel 1: QKV via mma.sync bf16 (hi/lo 3-term compensation).
// CTA 128m x 128n, 8 warps (2m x 4n), warp tile 64x32, k-tile 32,
// double-buffered cp.async. A smem [m][k] stride 40, B smem [n][k] stride 40
// (both conflict-free for the frag load pattern). Epilogue de-interleaves.
// ---------------------------------------------------------------------------
#define ASTR 40

__global__ __launch_bounds__(256, 2) void qkv_mma()
{
    __shared__ __align__(16) __nv_bfloat16 As[2][128*ASTR];
    __shared__ __align__(16) __nv_bfloat16 Bs[2][128*ASTR];

    const int z = blockIdx.z;
    const int m0 = blockIdx.x * 128;
    const int n0 = blockIdx.y * 128;
    const int tid = threadIdx.x;
    const int wid = tid >> 5, lane = tid & 31;
    const int wm = wid >> 2, wn = wid & 3;   // 2 x 4 warp grid
    const int lg = lane >> 2, lt = lane & 3; // group 0..7, idx 0..3

    const __nv_bfloat16* whi = g_wthi + (size_t)z * EH * DIN;
    const __nv_bfloat16* wlo = g_wtlo + (size_t)z * EH * DIN;

    const uint32_t sA = smem_u32(&As[0][0]);
    const uint32_t sB = smem_u32(&Bs[0][0]);

    auto fill = [&](int c, int buf) {
        const int pass = c >> 5;            // 0: hi*hi, 1: lo*hi, 2: hi*lo
        const int k0 = (c & 31) * 32;
        const __nv_bfloat16* A = (pass == 1) ? g_xlo : g_xhi;
        const __nv_bfloat16* B = (pass == 2) ? wlo : whi;
        const uint32_t ob = buf * (128 * ASTR * 2);
        #pragma unroll
        for (int l = 0; l < 2; l++) {
            int s = tid + l * 256, r = s >> 2, cg = s & 3;
            uint32_t off = ob + (r * ASTR + cg * 8) * 2;
            cpa16(sA + off, A + (size_t)(m0 + r) * DIN + k0 + cg * 8);
            cpa16(sB + off, B + (size_t)(n0 + r) * DIN + k0 + cg * 8);
        }
        cp_commit();
    };

    float acc[4][4][4] = {};   // [m-frag][n-frag][c-reg]

    fill(0, 0);
    for (int c = 0; c < 96; c++) {
        const int buf = c & 1;
        if (c < 95) { fill(c + 1, buf ^ 1); cp_wait<1>(); }
        else        cp_wait<0>();
        __syncthreads();

        const __nv_bfloat16* Ab = As[buf];
        const __nv_bfloat16* Bb = Bs[buf];
        #pragma unroll
        for (int ks = 0; ks < 2; ks++) {
            const int col = ks * 16 + lt * 2;
            uint32_t af[4][4], bf[4][2];
            #pragma unroll
            for (int i = 0; i < 4; i++) {
                int r = wm * 64 + i * 16 + lg;
                af[i][0] = *(const uint32_t*)(Ab + r * ASTR + col);
                af[i][1] = *(const uint32_t*)(Ab + (r + 8) * ASTR + col);
                af[i][2] = *(const uint32_t*)(Ab + r * ASTR + col + 8);
                af[i][3] = *(const uint32_t*)(Ab + (r + 8) * ASTR + col + 8);
            }
            #pragma unroll
            for (int j = 0; j < 4; j++) {
                int n = wn * 32 + j * 8 + lg;
                bf[j][0] = *(const uint32_t*)(Bb + n * ASTR + col);
                bf[j][1] = *(const uint32_t*)(Bb + n * ASTR + col + 8);
            }
            #pragma unroll
            for (int i = 0; i < 4; i++)
                #pragma unroll
                for (int j = 0; j < 4; j++)
                    mma_bf16(acc[i][j], af[i], bf[j]);
        }
        __syncthreads();
    }

    // epilogue: de-interleave heads (n = e*16 + h)
    float* dst = (z == 0) ? g_q : (z == 1) ? g_k : g_v;
    const int emajor = (z < 2);
    #pragma unroll
    for (int i = 0; i < 4; i++) {
        #pragma unroll
        for (int j = 0; j < 4; j++) {
            #pragma unroll
            for (int rr = 0; rr < 2; rr++) {
                int m = m0 + wm * 64 + i * 16 + lg + rr * 8;
                int b = m >> 11, t = m & 2047;
                #pragma unroll
                for (int cc = 0; cc < 2; cc++) {
                    int n = n0 + wn * 32 + j * 8 + lt * 2 + cc;
                    int e = n >> 4, h = n & 15;
                    size_t bh = (size_t)(b * HH + h);
                    float v = acc[i][j][rr * 2 + cc];
                    if (emajor) dst[(bh * EE + e) * TT + t] = v;
                    else        dst[(bh * TT + t) * EE + e] = v;
                }
            }
        }
    }
}

// ---------------------------------------------------------------------------
// Kernel 2: flash-attention, causal, cp.async split-wait pipeline (as R3).
// ---------------------------------------------------------------------------
__global__ __launch_bounds__(256, 2) void attn_kernel()
{
    extern __shared__ __align__(16) float sm[];
    float* Qs = sm;                    // [64 e][132] (128 r used)
    float* Ks = sm + 64*132;           // [64 e][68]
    float* Vs = sm + 64*132 + 64*68;   // [64 c][68]
    float* Ps = sm + 64*132 + 2*64*68; // [128 r][68]

    const int qt = (int)(gridDim.x - 1) - (int)blockIdx.x;
    const int bh = blockIdx.y;
    const int r0 = qt * 128;
    const int tid = threadIdx.x;
    const int ty = tid >> 4, tx = tid & 15;

    const float* qpl = g_q + (size_t)bh * (EE*TT);
    const float* kpl = g_k + (size_t)bh * (EE*TT);
    const float* vpl = g_v + (size_t)bh * (TT*EE);

    const uint32_t sK = smem_u32(Ks);
    const uint32_t sV = smem_u32(Vs);

    auto issueK = [&](int c0) {
        #pragma unroll
        for (int l = 0; l < 4; l++) {
            int s = tid + l*256, r = s >> 4, g = s & 15;
            cpa16(sK + (r*68 + g*4)*4, kpl + r * TT + c0 + g * 4);
        }
        cp_commit();
    };
    auto issueV = [&](int c0) {
        #pragma unroll
        for (int l = 0; l < 4; l++) {
            int s = tid + l*256, r = s >> 4, g = s & 15;
            cpa16(sV + (r*68 + g*4)*4, vpl + (c0 + r) * EE + g * 4);
        }
        cp_commit();
    };

    const int nkt = 2*qt + 2;
    issueK(0);
    issueV(0);

    for (int s = tid; s < 64*32; s += 256) {
        int er = s >> 5, cg = s & 31;
        float4 v4 = *(const float4*)(qpl + er * TT + r0 + cg * 4);
        v4.x *= 0.125f; v4.y *= 0.125f; v4.z *= 0.125f; v4.w *= 0.125f;
        *(float4*)(Qs + er*132 + cg*4) = v4;
    }

    float o[8][4] = {};
    float mi[8], li[8];
    #pragma unroll
    for (int i = 0; i < 8; i++) { mi[i] = -INFINITY; li[i] = 0.f; }

    for (int kt = 0; kt < nkt; kt++) {
        const int c0 = kt * 64;

        cp_wait<1>();
        __syncthreads();

        float s_[8][4] = {};
        #pragma unroll 8
        for (int e = 0; e < 64; e++) {
            float q[8], k[4];
            ld4(q,     Qs + e*132 + ty*4);
            ld4(q + 4, Qs + e*132 + 64 + ty*4);
            ld4(k,     Ks + e*68 + tx*4);
            #pragma unroll
            for (int i = 0; i < 8; i++)
                #pragma unroll
                for (int j = 0; j < 4; j++)
                    s_[i][j] += q[i] * k[j];
        }
        __syncthreads();
        issueK(kt + 1 < nkt ? c0 + 64 : 0);

        if (kt >= 2*qt) {
            #pragma unroll
            for (int i = 0; i < 8; i++) {
                int rg = r0 + (i >> 2)*64 + ty*4 + (i & 3);
                #pragma unroll
                for (int j = 0; j < 4; j++)
                    if (c0 + tx*4 + j > rg) s_[i][j] = -1e30f;
            }
        }

        #pragma unroll
        for (int i = 0; i < 8; i++) {
            float tm = fmaxf(fmaxf(s_[i][0], s_[i][1]), fmaxf(s_[i][2], s_[i][3]));
            #pragma unroll
            for (int off = 8; off > 0; off >>= 1)
                tm = fmaxf(tm, __shfl_xor_sync(0xffffffffu, tm, off));
            float nm = fmaxf(mi[i], tm);
            float corr = __expf(mi[i] - nm);
            float rs = 0.f;
            #pragma unroll
            for (int j = 0; j < 4; j++) {
                s_[i][j] = __expf(s_[i][j] - nm);
                rs += s_[i][j];
            }
            #pragma unroll
            for (int off = 8; off > 0; off >>= 1)
                rs += __shfl_xor_sync(0xffffffffu, rs, off);
            li[i] = li[i] * corr + rs;
            mi[i] = nm;
            #pragma unroll
            for (int j = 0; j < 4; j++) o[i][j] *= corr;
            int rr = (i >> 2)*64 + ty*4 + (i & 3);
            *(float4*)(Ps + rr*68 + tx*4) =
                make_float4(s_[i][0], s_[i][1], s_[i][2], s_[i][3]);
        }

        cp_wait<1>();
        __syncthreads();

        #pragma unroll 4
        for (int cb = 0; cb < 64; cb += 4) {
            float pr[8][4];
            #pragma unroll
            for (int i = 0; i < 8; i++) {
                int rr = (i >> 2)*64 + ty*4 + (i & 3);
                ld4(pr[i], Ps + rr*68 + cb);
            }
            #pragma unroll
            for (int cc = 0; cc < 4; cc++) {
                float v[4];
                ld4(v, Vs + (cb + cc)*68 + tx*4);
                #pragma unroll
                for (int i = 0; i < 8; i++)
                    #pragma unroll
                    for (int j = 0; j < 4; j++)
                        o[i][j] += pr[i][cc] * v[j];
            }
        }
        __syncthreads();
        issueV(kt + 1 < nkt ? c0 + 64 : 0);
    }

    #pragma unroll
    for (int i = 0; i < 8; i++) {
        float inv = 1.0f / li[i];
        int rr = (i >> 2)*64 + ty*4 + (i & 3);
        float4 r;
        r.x = o[i][0] * inv; r.y = o[i][1] * inv;
        r.z = o[i][2] * inv; r.w = o[i][3] * inv;
        *(float4*)(g_o + (size_t)bh * (TT*EE) + (size_t)(r0 + rr) * EE + tx*4) = r;
    }
}

// ---------------------------------------------------------------------------
// Kernel 3a: out = bias broadcast
// ---------------------------------------------------------------------------
__global__ __launch_bounds__(256) void init_out(const float* __restrict__ bu,
                                                float* __restrict__ out)
{
    int i = blockIdx.x * 256 + threadIdx.x;
    out[i] = bu[i & 63];
}

// ---------------------------------------------------------------------------
// Kernel 3b: output projection, split-K x4, atomicAdd reduce.
// ---------------------------------------------------------------------------
__global__ __launch_bounds__(256) void proj_kernel(
    const float* __restrict__ Wu,
    float* __restrict__ out)
{
    __shared__ __align__(16) float As[16*68];
    __shared__ __align__(16) float Bs[16*68];

    const int m0 = blockIdx.x * 64;
    const int kbase = blockIdx.y * 256;
    const int tid = threadIdx.x;
    const int ty = tid >> 4, tx = tid & 15;

    float acc[4][4] = {};

    for (int k0 = kbase; k0 < kbase + 256; k0 += 16) {
        const int e0 = k0 >> 4;
        for (int s = tid; s < 1024; s += 256) {
            int k = s >> 6, mm = s & 63;
            int gm = m0 + mm;
            int b = gm >> 11, t = gm & 2047;
            As[k*68 + mm] = g_o[(size_t)(b * HH + k) * (TT*EE) + (size_t)t * EE + e0];
        }
        {
            int k = tid >> 4, ng = tid & 15;
            *(float4*)(Bs + k*68 + ng*4) =
                *(const float4*)(Wu + (size_t)(k0 + k) * EE + ng * 4);
        }
        __syncthreads();

        #pragma unroll
        for (int k = 0; k < 16; k++) {
            float a[4], b[4];
            ld4(a, As + k*68 + ty*4);
            ld4(b, Bs + k*68 + tx*4);
            #pragma unroll
            for (int i = 0; i < 4; i++)
                #pragma unroll
                for (int j = 0; j < 4; j++)
                    acc[i][j] += a[i] * b[j];
        }
        __syncthreads();
    }

    #pragma unroll
    for (int i = 0; i < 4; i++) {
        int gm = m0 + ty*4 + i;
        #pragma unroll
        for (int j = 0; j < 4; j++)
            atomicAdd(out + (size_t)gm * EE + tx*4 + j, acc[i][j]);
    }
}

// ---------------------------------------------------------------------------
extern "C" void kernel_launch(void* const* d_in, const int* in_sizes, int n_in,
                              void* d_out, int out_size)
{
    const float* inp = (const float*)d_in[0];
    // d_in[1] is the causal mask; causality is implemented directly.
    const float* Wq = (const float*)d_in[2];
    const float* Wk = (const float*)d_in[3];
    const float* Wv = (const float*)d_in[4];
    const float* Wu = (const float*)d_in[5];
    const float* bu = (const float*)d_in[6];
    float* out = (float*)d_out;

    const int attn_smem = (64*132 + 2*64*68 + 128*68) * (int)sizeof(float);
    cudaFuncSetAttribute(attn_kernel,
                         cudaFuncAttributeMaxDynamicSharedMemorySize, attn_smem);

    conv_x<<<MM*DIN/1024, 256>>>(inp);
    conv_w<<<dim3(DIN/32, EH/32, 3), 256>>>(Wq, Wk, Wv);

    qkv_mma<<<dim3(MM/128, EH/128, 3), 256>>>();

    attn_kernel<<<dim3(TT/128, BB*HH), 256, attn_smem>>>();

    init_out<<<(MM*EE)/256, 256>>>(bu, out);
    proj_kernel<<<dim3(MM/64, 4), 256>>>(Wu, out);
}

// round 6
// speedup vs baseline: 2.2443x; 1.6055x over previous
#include <cuda_runtime.h>
#include <cuda_bf16.h>
#include <math.h>
#include <stdint.h>

#define BB 2
#define TT 2048
#define DIN 1024
#define EE 64
#define HH 16
#define EH 1024
#define MM (BB*TT)

// bf16 split operands for QKV GEMM
__device__ __align__(16) __nv_bfloat16 g_xhi[MM*DIN];
__device__ __align__(16) __nv_bfloat16 g_xlo[MM*DIN];
__device__ __align__(16) __nv_bfloat16 g_wthi[3*EH*DIN];   // [z][n][k]
__device__ __align__(16) __nv_bfloat16 g_wtlo[3*EH*DIN];
// fp32 staging: q,k in [b,h,t,e]; v in [b,h,e,t]
__device__ __align__(16) float g_qf[BB*HH*TT*EE];
__device__ __align__(16) float g_kf[BB*HH*TT*EE];
__device__ __align__(16) float g_vf[BB*HH*EE*TT];
// bf16 hi/lo for attention (q,k [b,h,t,e]; v [b,h,e,t]); q pre-scaled 0.125
__device__ __align__(16) __nv_bfloat16 g_qbh[BB*HH*TT*EE];
__device__ __align__(16) __nv_bfloat16 g_qbl[BB*HH*TT*EE];
__device__ __align__(16) __nv_bfloat16 g_kbh[BB*HH*TT*EE];
__device__ __align__(16) __nv_bfloat16 g_kbl[BB*HH*TT*EE];
__device__ __align__(16) __nv_bfloat16 g_vbh[BB*HH*EE*TT];
__device__ __align__(16) __nv_bfloat16 g_vbl[BB*HH*EE*TT];
// attention output [b,h,t,e] fp32
__device__ __align__(16) float g_o[BB*HH*TT*EE];

__device__ __forceinline__ void ld4(float* d, const float* s) {
    float4 t = *(const float4*)s;
    d[0] = t.x; d[1] = t.y; d[2] = t.z; d[3] = t.w;
}
__device__ __forceinline__ void cpa16(uint32_t dst, const void* src) {
    asm volatile("cp.async.cg.shared.global [%0], [%1], 16;\n" :: "r"(dst), "l"(src));
}
__device__ __forceinline__ void cp_commit() {
    asm volatile("cp.async.commit_group;\n");
}
template<int N> __device__ __forceinline__ void cp_wait() {
    asm volatile("cp.async.wait_group %0;\n" :: "n"(N));
}
__device__ __forceinline__ uint32_t smem_u32(const void* p) {
    uint32_t a;
    asm("{ .reg .u64 t; cvta.to.shared.u64 t, %1; cvt.u32.u64 %0, t; }" : "=r"(a) : "l"(p));
    return a;
}
__device__ __forceinline__ void mma_bf16(float* c, const uint32_t* a,
                                         uint32_t b0, uint32_t b1) {
    asm volatile(
        "mma.sync.aligned.m16n8k16.row.col.f32.bf16.bf16.f32 "
        "{%0,%1,%2,%3}, {%4,%5,%6,%7}, {%8,%9}, {%0,%1,%2,%3};"
        : "+f"(c[0]), "+f"(c[1]), "+f"(c[2]), "+f"(c[3])
        : "r"(a[0]), "r"(a[1]), "r"(a[2]), "r"(a[3]), "r"(b0), "r"(b1));
}
// pack (f0 -> low half, f1 -> high half) into bf16x2 hi + residual lo
__device__ __forceinline__ void pack_hilo(float f0, float f1,
                                          uint32_t& hi, uint32_t& lo) {
    __nv_bfloat162 h = __floats2bfloat162_rn(f0, f1);
    float r0 = f0 - __bfloat162float(h.x);
    float r1 = f1 - __bfloat162float(h.y);
    __nv_bfloat162 l = __floats2bfloat162_rn(r0, r1);
    hi = *reinterpret_cast<uint32_t*>(&h);
    lo = *reinterpret_cast<uint32_t*>(&l);
}

// ---------------------------------------------------------------------------
// Prep: X f32 -> bf16 hi/lo
// ---------------------------------------------------------------------------
__global__ __launch_bounds__(256) void conv_x(const float* __restrict__ x)
{
    int i = (blockIdx.x * 256 + threadIdx.x) * 4;
    float4 v = *(const float4*)(x + i);
    uint32_t h01, l01, h23, l23;
    pack_hilo(v.x, v.y, h01, l01);
    pack_hilo(v.z, v.w, h23, l23);
    *(uint32_t*)(g_xhi + i)     = h01;
    *(uint32_t*)(g_xhi + i + 2) = h23;
    *(uint32_t*)(g_xlo + i)     = l01;
    *(uint32_t*)(g_xlo + i + 2) = l23;
}

// ---------------------------------------------------------------------------
// Prep: W [k][n] f32 -> Wt [n][k] bf16 hi/lo, for each of Wq,Wk,Wv
// ---------------------------------------------------------------------------
__global__ __launch_bounds__(256) void conv_w(
    const float* __restrict__ Wq, const float* __restrict__ Wk,
    const float* __restrict__ Wv)
{
    const int z = blockIdx.z;
    const float* W = (z == 0) ? Wq : (z == 1) ? Wk : Wv;
    __shared__ float t[32][33];
    const int k0 = blockIdx.x * 32, n0 = blockIdx.y * 32;
    const int x = threadIdx.x & 31, y = threadIdx.x >> 5;
    #pragma unroll
    for (int i = 0; i < 32; i += 8)
        t[y + i][x] = W[(k0 + y + i) * EH + n0 + x];
    __syncthreads();
    #pragma unroll
    for (int i = 0; i < 32; i += 8) {
        float v = t[x][y + i];
        __nv_bfloat16 hi = __float2bfloat16(v);
        __nv_bfloat16 lo = __float2bfloat16(v - __bfloat162float(hi));
        size_t idx = (size_t)z * EH * DIN + (size_t)(n0 + y + i) * DIN + k0 + x;
        g_wthi[idx] = hi;
        g_wtlo[idx] = lo;
    }
}

// ---------------------------------------------------------------------------
// Kernel 1: QKV via mma.sync bf16 (hi/lo 3-term compensation).
// CTA 128m x 128n, 8 warps (2m x 4n), warp tile 64x32, k-tile 32.
// Epilogue: q,k -> [b,h,t,e] fp32; v -> [b,h,e,t] fp32.
// ---------------------------------------------------------------------------
#define ASTR 40

__global__ __launch_bounds__(256, 2) void qkv_mma()
{
    __shared__ __align__(16) __nv_bfloat16 As[2][128*ASTR];
    __shared__ __align__(16) __nv_bfloat16 Bs[2][128*ASTR];

    const int z = blockIdx.z;
    const int m0 = blockIdx.x * 128;
    const int n0 = blockIdx.y * 128;
    const int tid = threadIdx.x;
    const int wid = tid >> 5, lane = tid & 31;
    const int wm = wid >> 2, wn = wid & 3;
    const int lg = lane >> 2, lt = lane & 3;

    const __nv_bfloat16* whi = g_wthi + (size_t)z * EH * DIN;
    const __nv_bfloat16* wlo = g_wtlo + (size_t)z * EH * DIN;

    const uint32_t sA = smem_u32(&As[0][0]);
    const uint32_t sB = smem_u32(&Bs[0][0]);

    auto fill = [&](int c, int buf) {
        const int pass = c >> 5;
        const int k0 = (c & 31) * 32;
        const __nv_bfloat16* A = (pass == 1) ? g_xlo : g_xhi;
        const __nv_bfloat16* B = (pass == 2) ? wlo : whi;
        const uint32_t ob = buf * (128 * ASTR * 2);
        #pragma unroll
        for (int l = 0; l < 2; l++) {
            int s = tid + l * 256, r = s >> 2, cg = s & 3;
            uint32_t off = ob + (r * ASTR + cg * 8) * 2;
            cpa16(sA + off, A + (size_t)(m0 + r) * DIN + k0 + cg * 8);
            cpa16(sB + off, B + (size_t)(n0 + r) * DIN + k0 + cg * 8);
        }
        cp_commit();
    };

    float acc[4][4][4] = {};

    fill(0, 0);
    for (int c = 0; c < 96; c++) {
        const int buf = c & 1;
        if (c < 95) { fill(c + 1, buf ^ 1); cp_wait<1>(); }
        else        cp_wait<0>();
        __syncthreads();

        const __nv_bfloat16* Ab = As[buf];
        const __nv_bfloat16* Bb = Bs[buf];
        #pragma unroll
        for (int ks = 0; ks < 2; ks++) {
            const int col = ks * 16 + lt * 2;
            uint32_t af[4][4], bf[4][2];
            #pragma unroll
            for (int i = 0; i < 4; i++) {
                int r = wm * 64 + i * 16 + lg;
                af[i][0] = *(const uint32_t*)(Ab + r * ASTR + col);
                af[i][1] = *(const uint32_t*)(Ab + (r + 8) * ASTR + col);
                af[i][2] = *(const uint32_t*)(Ab + r * ASTR + col + 8);
                af[i][3] = *(const uint32_t*)(Ab + (r + 8) * ASTR + col + 8);
            }
            #pragma unroll
            for (int j = 0; j < 4; j++) {
                int n = wn * 32 + j * 8 + lg;
                bf[j][0] = *(const uint32_t*)(Bb + n * ASTR + col);
                bf[j][1] = *(const uint32_t*)(Bb + n * ASTR + col + 8);
            }
            #pragma unroll
            for (int i = 0; i < 4; i++)
                #pragma unroll
                for (int j = 0; j < 4; j++)
                    mma_bf16(acc[i][j], af[i], bf[j][0], bf[j][1]);
        }
        __syncthreads();
    }

    // epilogue: de-interleave heads (n = e*16 + h).
    float* dst = (z == 0) ? g_qf : (z == 1) ? g_kf : g_vf;
    const int emajor = (z == 2);   // v -> [b,h,e,t]; q,k -> [b,h,t,e]
    #pragma unroll
    for (int i = 0; i < 4; i++) {
        #pragma unroll
        for (int j = 0; j < 4; j++) {
            #pragma unroll
            for (int rr = 0; rr < 2; rr++) {
                int m = m0 + wm * 64 + i * 16 + lg + rr * 8;
                int b = m >> 11, t = m & 2047;
                #pragma unroll
                for (int cc = 0; cc < 2; cc++) {
                    int n = n0 + wn * 32 + j * 8 + lt * 2 + cc;
                    int e = n >> 4, h = n & 15;
                    size_t bh = (size_t)(b * HH + h);
                    float v = acc[i][j][rr * 2 + cc];
                    if (emajor) dst[(bh * EE + e) * TT + t] = v;
                    else        dst[(bh * TT + t) * EE + e] = v;
                }
            }
        }
    }
}

// ---------------------------------------------------------------------------
// conv_qkv: fp32 staging -> bf16 hi/lo (layout-preserving; Q scaled 0.125)
// ---------------------------------------------------------------------------
__global__ __launch_bounds__(256) void conv_qkv()
{
    const int z = blockIdx.y;
    const float* src = (z == 0) ? g_qf : (z == 1) ? g_kf : g_vf;
    __nv_bfloat16* dh = (z == 0) ? g_qbh : (z == 1) ? g_kbh : g_vbh;
    __nv_bfloat16* dl = (z == 0) ? g_qbl : (z == 1) ? g_kbl : g_vbl;
    const float sc = (z == 0) ? 0.125f : 1.0f;
    size_t i = ((size_t)blockIdx.x * 256 + threadIdx.x) * 4;
    float4 v = *(const float4*)(src + i);
    v.x *= sc; v.y *= sc; v.z *= sc; v.w *= sc;
    uint32_t h01, l01, h23, l23;
    pack_hilo(v.x, v.y, h01, l01);
    pack_hilo(v.z, v.w, h23, l23);
    *(uint32_t*)(dh + i)     = h01;
    *(uint32_t*)(dh + i + 2) = h23;
    *(uint32_t*)(dl + i)     = l01;
    *(uint32_t*)(dl + i + 2) = l23;
}

// ---------------------------------------------------------------------------
// Kernel 2: flash-attention on mma.sync, causal, hi/lo compensated.
// CTA = 128 rows of one (b,h); 8 warps x 16 rows; key tiles of 64.
// K smem [c][e], V smem [e][c], stride 72 (conflict-free). P stays in regs.
// ---------------------------------------------------------------------------
#define KSTR 72

__global__ __launch_bounds__(256) void attn_mma()
{
    __shared__ __align__(16) __nv_bfloat16 sKh[64*KSTR];
    __shared__ __align__(16) __nv_bfloat16 sKl[64*KSTR];
    __shared__ __align__(16) __nv_bfloat16 sVh[64*KSTR];
    __shared__ __align__(16) __nv_bfloat16 sVl[64*KSTR];

    const int qt = (int)(gridDim.x - 1) - (int)blockIdx.x;  // big tiles first
    const int bh = blockIdx.y;
    const int r0 = qt * 128;
    const int tid = threadIdx.x;
    const int wid = tid >> 5, lane = tid & 31;
    const int lg = lane >> 2, lt = lane & 3;

    const uint32_t uKh = smem_u32(sKh), uKl = smem_u32(sKl);
    const uint32_t uVh = smem_u32(sVh), uVl = smem_u32(sVl);

    auto issueK = [&](int c0) {
        #pragma unroll
        for (int l = 0; l < 4; l++) {
            int s = tid + l * 256;
            int arr = s >> 9, idx = s & 511;
            int r = idx >> 3, g = idx & 7;
            const __nv_bfloat16* src = (arr ? g_kbl : g_kbh)
                + ((size_t)bh * TT + c0 + r) * EE + g * 8;
            cpa16((arr ? uKl : uKh) + (r * KSTR + g * 8) * 2, src);
        }
        cp_commit();
    };
    auto issueV = [&](int c0) {
        #pragma unroll
        for (int l = 0; l < 4; l++) {
            int s = tid + l * 256;
            int arr = s >> 9, idx = s & 511;
            int r = idx >> 3, g = idx & 7;
            const __nv_bfloat16* src = (arr ? g_vbl : g_vbh)
                + ((size_t)bh * EE + r) * TT + c0 + g * 8;
            cpa16((arr ? uVl : uVh) + (r * KSTR + g * 8) * 2, src);
        }
        cp_commit();
    };

    const int nkt = 2 * qt + 2;
    issueK(0);
    issueV(0);

    // Q fragments, register-resident for the whole CTA (Q pre-scaled 1/8)
    const int ra = r0 + wid * 16 + lg, rb = ra + 8;
    uint32_t qh[4][4], ql[4][4];
    {
        const __nv_bfloat16* qhp = g_qbh + (size_t)bh * TT * EE;
        const __nv_bfloat16* qlp = g_qbl + (size_t)bh * TT * EE;
        #pragma unroll
        for (int ks = 0; ks < 4; ks++) {
            int e0 = ks * 16 + 2 * lt;
            qh[ks][0] = *(const uint32_t*)(qhp + (size_t)ra * EE + e0);
            qh[ks][1] = *(const uint32_t*)(qhp + (size_t)rb * EE + e0);
            qh[ks][2] = *(const uint32_t*)(qhp + (size_t)ra * EE + e0 + 8);
            qh[ks][3] = *(const uint32_t*)(qhp + (size_t)rb * EE + e0 + 8);
            ql[ks][0] = *(const uint32_t*)(qlp + (size_t)ra * EE + e0);
            ql[ks][1] = *(const uint32_t*)(qlp + (size_t)rb * EE + e0);
            ql[ks][2] = *(const uint32_t*)(qlp + (size_t)ra * EE + e0 + 8);
            ql[ks][3] = *(const uint32_t*)(qlp + (size_t)rb * EE + e0 + 8);
        }
    }

    float os[8][4] = {};
    float mi_a = -INFINITY, mi_b = -INFINITY, li_a = 0.f, li_b = 0.f;

    for (int kt = 0; kt < nkt; kt++) {
        const int c0 = kt * 64;

        cp_wait<1>();       // K(kt) ready; V(kt) may be in flight
        __syncthreads();

        // S = Q K^T (3 compensated terms), 16x64 per warp
        float cs[8][4] = {};
        #pragma unroll
        for (int ks = 0; ks < 4; ks++) {
            const int col = ks * 16 + 2 * lt;
            #pragma unroll
            for (int jt = 0; jt < 8; jt++) {
                const int rk = (jt * 8 + lg) * KSTR + col;
                uint32_t kh0 = *(const uint32_t*)(sKh + rk);
                uint32_t kh1 = *(const uint32_t*)(sKh + rk + 8);
                uint32_t kl0 = *(const uint32_t*)(sKl + rk);
                uint32_t kl1 = *(const uint32_t*)(sKl + rk + 8);
                mma_bf16(cs[jt], qh[ks], kh0, kh1);
                mma_bf16(cs[jt], ql[ks], kh0, kh1);
                mma_bf16(cs[jt], qh[ks], kl0, kl1);
            }
        }
        __syncthreads();                       // all warps done with K smem
        issueK(kt + 1 < nkt ? c0 + 64 : 0);    // overlaps softmax + PV

        if (kt >= 2 * qt) {  // causal mask (only last two tiles)
            #pragma unroll
            for (int jt = 0; jt < 8; jt++)
                #pragma unroll
                for (int cc = 0; cc < 2; cc++) {
                    int col = c0 + jt * 8 + 2 * lt + cc;
                    if (col > ra) cs[jt][cc]     = -1e30f;
                    if (col > rb) cs[jt][2 + cc] = -1e30f;
                }
        }

        // online softmax over rows ra (cs[..][0,1]) and rb (cs[..][2,3])
        float ma = -1e30f, mb = -1e30f;
        #pragma unroll
        for (int jt = 0; jt < 8; jt++) {
            ma = fmaxf(ma, fmaxf(cs[jt][0], cs[jt][1]));
            mb = fmaxf(mb, fmaxf(cs[jt][2], cs[jt][3]));
        }
        ma = fmaxf(ma, __shfl_xor_sync(0xffffffffu, ma, 1));
        ma = fmaxf(ma, __shfl_xor_sync(0xffffffffu, ma, 2));
        mb = fmaxf(mb, __shfl_xor_sync(0xffffffffu, mb, 1));
        mb = fmaxf(mb, __shfl_xor_sync(0xffffffffu, mb, 2));
        float nma = fmaxf(mi_a, ma), nmb = fmaxf(mi_b, mb);
        float ca = __expf(mi_a - nma), cb = __expf(mi_b - nmb);
        float sa = 0.f, sb = 0.f;
        #pragma unroll
        for (int jt = 0; jt < 8; jt++) {
            cs[jt][0] = __expf(cs[jt][0] - nma); sa += cs[jt][0];
            cs[jt][1] = __expf(cs[jt][1] - nma); sa += cs[jt][1];
            cs[jt][2] = __expf(cs[jt][2] - nmb); sb += cs[jt][2];
            cs[jt][3] = __expf(cs[jt][3] - nmb); sb += cs[jt][3];
        }
        sa += __shfl_xor_sync(0xffffffffu, sa, 1);
        sa += __shfl_xor_sync(0xffffffffu, sa, 2);
        sb += __shfl_xor_sync(0xffffffffu, sb, 1);
        sb += __shfl_xor_sync(0xffffffffu, sb, 2);
        li_a = li_a * ca + sa; mi_a = nma;
        li_b = li_b * cb + sb; mi_b = nmb;
        #pragma unroll
        for (int jt = 0; jt < 8; jt++) {
            os[jt][0] *= ca; os[jt][1] *= ca;
            os[jt][2] *= cb; os[jt][3] *= cb;
        }

        // P fragments (hi/lo) straight from registers
        uint32_t phi[4][4], plo[4][4];
        #pragma unroll
        for (int cc = 0; cc < 4; cc++) {
            pack_hilo(cs[2*cc][0],   cs[2*cc][1],   phi[cc][0], plo[cc][0]);
            pack_hilo(cs[2*cc][2],   cs[2*cc][3],   phi[cc][1], plo[cc][1]);
            pack_hilo(cs[2*cc+1][0], cs[2*cc+1][1], phi[cc][2], plo[cc][2]);
            pack_hilo(cs[2*cc+1][2], cs[2*cc+1][3], phi[cc][3], plo[cc][3]);
        }

        cp_wait<1>();       // V(kt) ready; K(kt+1) may be in flight
        __syncthreads();

        // O += P V (3 compensated terms)
        #pragma unroll
        for (int cc = 0; cc < 4; cc++) {
            const int col = cc * 16 + 2 * lt;
            #pragma unroll
            for (int jt = 0; jt < 8; jt++) {
                const int rv = (jt * 8 + lg) * KSTR + col;
                uint32_t vh0 = *(const uint32_t*)(sVh + rv);
                uint32_t vh1 = *(const uint32_t*)(sVh + rv + 8);
                uint32_t vl0 = *(const uint32_t*)(sVl + rv);
                uint32_t vl1 = *(const uint32_t*)(sVl + rv + 8);
                mma_bf16(os[jt], phi[cc], vh0, vh1);
                mma_bf16(os[jt], plo[cc], vh0, vh1);
                mma_bf16(os[jt], phi[cc], vl0, vl1);
            }
        }
        __syncthreads();                       // all warps done with V smem
        issueV(kt + 1 < nkt ? c0 + 64 : 0);
    }

    // epilogue: normalize, write [b,h,t,e]
    const float ia = 1.0f / li_a, ib = 1.0f / li_b;
    #pragma unroll
    for (int jt = 0; jt < 8; jt++) {
        int e0 = jt * 8 + 2 * lt;
        float2 wa = make_float2(os[jt][0] * ia, os[jt][1] * ia);
        float2 wb = make_float2(os[jt][2] * ib, os[jt][3] * ib);
        *(float2*)(g_o + ((size_t)bh * TT + ra) * EE + e0) = wa;
        *(float2*)(g_o + ((size_t)bh * TT + rb) * EE + e0) = wb;
    }
}

// ---------------------------------------------------------------------------
// Kernel 3a: out = bias broadcast
// ---------------------------------------------------------------------------
__global__ __launch_bounds__(256) void init_out(const float* __restrict__ bu,
                                                float* __restrict__ out)
{
    int i = blockIdx.x * 256 + threadIdx.x;
    out[i] = bu[i & 63];
}

// ---------------------------------------------------------------------------
// Kernel 3b: output projection, split-K x4, atomicAdd reduce.
// ---------------------------------------------------------------------------
__global__ __launch_bounds__(256) void proj_kernel(
    const float* __restrict__ Wu,
    float* __restrict__ out)
{
    __shared__ __align__(16) float As[16*68];
    __shared__ __align__(16) float Bs[16*68];

    const int m0 = blockIdx.x * 64;
    const int kbase = blockIdx.y * 256;
    const int tid = threadIdx.x;
    const int ty = tid >> 4, tx = tid & 15;

    float acc[4][4] = {};

    for (int k0 = kbase; k0 < kbase + 256; k0 += 16) {
        const int e0 = k0 >> 4;
        for (int s = tid; s < 1024; s += 256) {
            int k = s >> 6, mm = s & 63;
            int gm = m0 + mm;
            int b = gm >> 11, t = gm & 2047;
            As[k*68 + mm] = g_o[(size_t)(b * HH + k) * (TT*EE) + (size_t)t * EE + e0];
        }
        {
            int k = tid >> 4, ng = tid & 15;
            *(float4*)(Bs + k*68 + ng*4) =
                *(const float4*)(Wu + (size_t)(k0 + k) * EE + ng * 4);
        }
        __syncthreads();

        #pragma unroll
        for (int k = 0; k < 16; k++) {
            float a[4], b[4];
            ld4(a, As + k*68 + ty*4);
            ld4(b, Bs + k*68 + tx*4);
            #pragma unroll
            for (int i = 0; i < 4; i++)
                #pragma unroll
                for (int j = 0; j < 4; j++)
                    acc[i][j] += a[i] * b[j];
        }
        __syncthreads();
    }

    #pragma unroll
    for (int i = 0; i < 4; i++) {
        int gm = m0 + ty*4 + i;
        #pragma unroll
        for (int j = 0; j < 4; j++)
            atomicAdd(out + (size_t)gm * EE + tx*4 + j, acc[i][j]);
    }
}

// ---------------------------------------------------------------------------
extern "C" void kernel_launch(void* const* d_in, const int* in_sizes, int n_in,
                              void* d_out, int out_size)
{
    const float* inp = (const float*)d_in[0];
    // d_in[1] is the causal mask; causality is implemented directly.
    const float* Wq = (const float*)d_in[2];
    const float* Wk = (const float*)d_in[3];
    const float* Wv = (const float*)d_in[4];
    const float* Wu = (const float*)d_in[5];
    const float* bu = (const float*)d_in[6];
    float* out = (float*)d_out;

    conv_x<<<MM*DIN/1024, 256>>>(inp);
    conv_w<<<dim3(DIN/32, EH/32, 3), 256>>>(Wq, Wk, Wv);

    qkv_mma<<<dim3(MM/128, EH/128, 3), 256>>>();

    conv_qkv<<<dim3(MM*EE*HH/1024, 3), 256>>>();

    attn_mma<<<dim3(TT/128, BB*HH), 256>>>();

    init_out<<<(MM*EE)/256, 256>>>(bu, out);
    proj_kernel<<<dim3(MM/64, 4), 256>>>(Wu, out);
}